// round 17
// baseline (speedup 1.0000x reference)
#include <cuda_runtime.h>
#include <cstdint>

// ---------------------------------------------------------------------------
// PestDetectionSNN — R17: dual-pipe hybrid GEMM, fix of R16's B-frag load bug
// (R16 loaded W1 frags at raw index h*4+j = plane0/all-n instead of
//  k8p*512 + (n0+nn)*4 + li; store-side decomposition was already correct).
//   Pass 0: W1 -> tf32 hi/lo frag-ready layout (R12 verbatim, validated)
//   Pass 1: snn_gemm_hybrid, 800 CTAs x 256 thr, warp-specialized:
//     warps 0-3: scalar fp32 GEMM, k in [0,512)    -> fma pipe
//     warps 4-7: 3xTF32 mma.sync,  k in [512,1024) -> tensor pipe
//     one joint __syncthreads per kb; join; combine in smem; single write.
//   Pass 2: per-batch LIF scans (unchanged, 13.6us)
// ---------------------------------------------------------------------------

#define B_  256
#define T_  100
#define D_  1024
#define H_  128
#define C_  5
#define MT  (B_ * T_)          // 25600 GEMM rows

#define DECAY1 0.90483741803595952865f
#define DECAY2 0.95122942450071400910f

__device__ float g_Z[MT * H_];
// W1 frag images (R12 layout): per kb(16k): [k8][n][l4] float4=(hi_k,lo_k,hi_k+4,lo_k+4)
__device__ __align__(16) float g_W1p[64 * 4096];

// ---- helpers --------------------------------------------------------------
__device__ __forceinline__ float to_tf32(float x) {
    unsigned r;
    asm("cvt.rna.tf32.f32 %0, %1;" : "=r"(r) : "r"(__float_as_uint(x)));
    return __uint_as_float(r);
}

// mma.sync m16n8k8 tf32, D += A*B (C==D registers)
#define MMA_TF32(d, a, b)                                                   \
    asm volatile(                                                           \
        "mma.sync.aligned.m16n8k8.row.col.f32.tf32.tf32.f32 "               \
        "{%0,%1,%2,%3}, {%4,%5,%6,%7}, {%8,%9}, {%0,%1,%2,%3};"             \
        : "+f"((d)[0]), "+f"((d)[1]), "+f"((d)[2]), "+f"((d)[3])            \
        : "r"((a)[0]), "r"((a)[1]), "r"((a)[2]), "r"((a)[3]),               \
          "r"((b)[0]), "r"((b)[1]))

// ---------------------------------------------------------------------------
// Pass 0: W1 -> hi/lo frag layout (R12 verbatim; validated by R12 PASS).
// ---------------------------------------------------------------------------
__global__ __launch_bounds__(256) void w1_convert(const float* __restrict__ W1)
{
    const int idx = blockIdx.x * 256 + threadIdx.x;   // 0..65535
    const int n  = idx & 127;
    const int l4 = (idx >> 7) & 3;
    const int k8 = (idx >> 9) & 1;
    const int kb = idx >> 10;
    const int k  = kb * 16 + k8 * 8 + l4;
    const float w0 = W1[k * H_ + n];
    const float w4 = W1[(k + 4) * H_ + n];
    const float h0 = to_tf32(w0), e0 = to_tf32(w0 - h0);
    const float h4 = to_tf32(w4), e4 = to_tf32(w4 - h4);
    *(float4*)&g_W1p[kb * 4096 + k8 * 2048 + n * 16 + l4 * 4] =
        make_float4(h0, e0, h4, e4);
}

// ---------------------------------------------------------------------------
// Pass 1: hybrid GEMM. Tile 64(M) x 64(N) per CTA, grid 400 x 2 = 800.
// smF: A buffers @0/@1088 (16x68 each), B buffers @2176/@3200 (16x64 each);
//      Fres aliases smF[0..4095] after the loop.
// smH: two 4096-float buffers; each: A frags @0 (2 planes x 64 x 16),
//      B frags @2048.
// ---------------------------------------------------------------------------
__global__ __launch_bounds__(256, 2) void snn_gemm_hybrid(
    const float* __restrict__ A, const float* __restrict__ W1)
{
    __shared__ __align__(16) float smF[4224];
    __shared__ __align__(16) float smH[8192];

    const int tid  = threadIdx.x;
    const int wid  = tid >> 5;
    const int lane = tid & 31;
    const int bx   = blockIdx.x;
    const int m0   = (bx >> 1) * 64;
    const int n0   = (bx & 1) * 64;
    const bool isF = (wid < 4);

    // ---- F-side maps (meaningful for tid < 128) ----
    const int f_ar  = tid >> 1;             // A row 0..63
    const int f_ac8 = (tid & 1) << 3;       // A k-col 0 or 8
    const int f_br  = (tid & 127) >> 3;     // B k-row 0..15
    const int f_bc  = (tid & 7) << 3;       // B n-col 0..56
    const int f_ty  = (tid & 127) >> 3;     // micro M group 0..15
    const int f_tx  = tid & 7;              // micro N group 0..7
    const float* ApF = A  + (size_t)(m0 + f_ar) * D_ + f_ac8;
    const float* BpF = W1 + (size_t)f_br * H_ + n0 + f_bc;

    // ---- H-side maps (meaningful for tid >= 128) ----
    const int h      = tid & 127;
    const int arow   = h >> 1;              // 0..63
    const int aplane = h & 1;               // k8 plane
    const int hw     = wid - 4;
    const int wm     = hw >> 1, wn2 = hw & 1;
    const int g      = lane >> 2, l4 = lane & 3;
    const float* ApH = A + (size_t)(m0 + arow) * D_ + 512 + aplane * 8;

    // H-side W1-frag load indices: q = h*4+j -> (k8p, nn, li);
    // float4 index in chunk image = k8p*512 + (n0+nn)*4 + li   (R15 formula)
    int wq[4];
#pragma unroll
    for (int j = 0; j < 4; j++) {
        const int q   = h * 4 + j;              // 0..511
        const int k8p = q >> 8, nn = (q >> 2) & 63, li = q & 3;
        wq[j] = k8p * 512 + (n0 + nn) * 4 + li;
    }

    // prefetch registers (each group uses its own set)
    float4 pa0, pa1, pb0, pb1;            // F
    float4 hva, hvb, hwv[4];              // H

    // accumulators
    float accT[4][8] = {};      // F running totals
    float accH[2][4][4] = {};   // H mma accumulators

    // ================= prologue: stage chunk 0 into buffer 0 =================
    if (isF) {
        pa0 = *(const float4*)(ApF);
        pa1 = *(const float4*)(ApF + 4);
        pb0 = *(const float4*)(BpF);
        pb1 = *(const float4*)(BpF + 4);
        float av[8] = {pa0.x,pa0.y,pa0.z,pa0.w,pa1.x,pa1.y,pa1.z,pa1.w};
#pragma unroll
        for (int i = 0; i < 8; i++) smF[(f_ac8 + i) * 68 + f_ar] = av[i];
        *(float4*)&smF[2176 + f_br * 64 + f_bc]     = pb0;
        *(float4*)&smF[2176 + f_br * 64 + f_bc + 4] = pb1;
    } else {
        hva = *(const float4*)(ApH);
        hvb = *(const float4*)(ApH + 4);
        const float4* wsrc = (const float4*)&g_W1p[32 * 4096];
#pragma unroll
        for (int j = 0; j < 4; j++) hwv[j] = wsrc[wq[j]];
        float av[8] = {hva.x,hva.y,hva.z,hva.w,hvb.x,hvb.y,hvb.z,hvb.w};
#pragma unroll
        for (int i = 0; i < 8; i++) {
            const float hi = to_tf32(av[i]);
            const float lo = to_tf32(av[i] - hi);
            const int off  = (i & 3) * 4 + (i >> 2) * 2;
            *(float2*)&smH[aplane * 1024 + arow * 16 + off] = make_float2(hi, lo);
        }
#pragma unroll
        for (int j = 0; j < 4; j++) {
            const int q = h * 4 + j;                 // 0..511
            const int k8p = q >> 8, nn = (q >> 2) & 63, li = q & 3;
            *(float4*)&smH[2048 + k8p * 1024 + nn * 16 + li * 4] = hwv[j];
        }
    }
    __syncthreads();

    // ================= main loop: 32 chunks of 16 k =================
    int buf = 0;
    for (int kb = 0; kb < 32; kb++) {
        // ---- prefetch chunk kb+1 ----
        if (kb < 31) {
            if (isF) {
                pa0 = *(const float4*)(ApF + (kb + 1) * 16);
                pa1 = *(const float4*)(ApF + (kb + 1) * 16 + 4);
                pb0 = *(const float4*)(BpF + (size_t)((kb + 1) * 16) * H_);
                pb1 = *(const float4*)(BpF + (size_t)((kb + 1) * 16) * H_ + 4);
            } else {
                hva = *(const float4*)(ApH + (kb + 1) * 16);
                hvb = *(const float4*)(ApH + (kb + 1) * 16 + 4);
                const float4* wsrc = (const float4*)&g_W1p[(33 + kb) * 4096];
#pragma unroll
                for (int j = 0; j < 4; j++) hwv[j] = wsrc[wq[j]];
            }
        }

        // ---- compute on current buffer ----
        if (isF) {
            float accB[4][8] = {};
            const float* asb = &smF[buf * 1088];
            const float* bsb = &smF[2176 + buf * 1024];
#pragma unroll
            for (int k = 0; k < 16; k++) {
                float4 av  = *(const float4*)&asb[k * 68 + f_ty * 4];
                float4 bv0 = *(const float4*)&bsb[k * 64 + f_tx * 8];
                float4 bv1 = *(const float4*)&bsb[k * 64 + f_tx * 8 + 4];
                float am[4] = {av.x, av.y, av.z, av.w};
                float bn[8] = {bv0.x, bv0.y, bv0.z, bv0.w,
                               bv1.x, bv1.y, bv1.z, bv1.w};
#pragma unroll
                for (int m = 0; m < 4; m++)
#pragma unroll
                    for (int n = 0; n < 8; n++)
                        accB[m][n] = fmaf(am[m], bn[n], accB[m][n]);
            }
#pragma unroll
            for (int m = 0; m < 4; m++)
#pragma unroll
                for (int n = 0; n < 8; n++)
                    accT[m][n] = __fadd_rn(accT[m][n], accB[m][n]);
        } else {
            const float* hb = &smH[buf * 4096];
#pragma unroll
            for (int k8 = 0; k8 < 2; k8++) {
                unsigned ah[2][4], al[2][4];
#pragma unroll
                for (int mi = 0; mi < 2; mi++) {
                    const int r0 = wm * 32 + mi * 16 + g;
                    float4 v0 = *(const float4*)&hb[k8 * 1024 + r0 * 16 + l4 * 4];
                    float4 v1 = *(const float4*)&hb[k8 * 1024 + (r0 + 8) * 16 + l4 * 4];
                    ah[mi][0] = __float_as_uint(v0.x); ah[mi][1] = __float_as_uint(v1.x);
                    ah[mi][2] = __float_as_uint(v0.z); ah[mi][3] = __float_as_uint(v1.z);
                    al[mi][0] = __float_as_uint(v0.y); al[mi][1] = __float_as_uint(v1.y);
                    al[mi][2] = __float_as_uint(v0.w); al[mi][3] = __float_as_uint(v1.w);
                }
                unsigned bh[4][2], bl[4][2];
#pragma unroll
                for (int ni = 0; ni < 4; ni++) {
                    const int nr = wn2 * 32 + ni * 8 + g;
                    float4 v = *(const float4*)&hb[2048 + k8 * 1024 + nr * 16 + l4 * 4];
                    bh[ni][0] = __float_as_uint(v.x); bh[ni][1] = __float_as_uint(v.z);
                    bl[ni][0] = __float_as_uint(v.y); bl[ni][1] = __float_as_uint(v.w);
                }
#pragma unroll
                for (int mi = 0; mi < 2; mi++)
#pragma unroll
                    for (int ni = 0; ni < 4; ni++)
                        MMA_TF32(accH[mi][ni], ah[mi], bh[ni]);
#pragma unroll
                for (int mi = 0; mi < 2; mi++)
#pragma unroll
                    for (int ni = 0; ni < 4; ni++)
                        MMA_TF32(accH[mi][ni], al[mi], bh[ni]);
#pragma unroll
                for (int mi = 0; mi < 2; mi++)
#pragma unroll
                    for (int ni = 0; ni < 4; ni++)
                        MMA_TF32(accH[mi][ni], ah[mi], bl[ni]);
            }
        }

        // ---- stage chunk kb+1 into the other buffer; joint sync ----
        if (kb < 31) {
            const int nb = buf ^ 1;
            if (isF) {
                float av[8] = {pa0.x,pa0.y,pa0.z,pa0.w,pa1.x,pa1.y,pa1.z,pa1.w};
#pragma unroll
                for (int i = 0; i < 8; i++)
                    smF[nb * 1088 + (f_ac8 + i) * 68 + f_ar] = av[i];
                *(float4*)&smF[2176 + nb * 1024 + f_br * 64 + f_bc]     = pb0;
                *(float4*)&smF[2176 + nb * 1024 + f_br * 64 + f_bc + 4] = pb1;
            } else {
                float av[8] = {hva.x,hva.y,hva.z,hva.w,hvb.x,hvb.y,hvb.z,hvb.w};
#pragma unroll
                for (int i = 0; i < 8; i++) {
                    const float hi = to_tf32(av[i]);
                    const float lo = to_tf32(av[i] - hi);
                    const int off  = (i & 3) * 4 + (i >> 2) * 2;
                    *(float2*)&smH[nb * 4096 + aplane * 1024 + arow * 16 + off] =
                        make_float2(hi, lo);
                }
#pragma unroll
                for (int j = 0; j < 4; j++) {
                    const int q = h * 4 + j;
                    const int k8p = q >> 8, nn = (q >> 2) & 63, li = q & 3;
                    *(float4*)&smH[nb * 4096 + 2048 + k8p * 1024 + nn * 16 + li * 4] = hwv[j];
                }
            }
            __syncthreads();
            buf = nb;
        }
    }

    __syncthreads();   // F warps done reading smF; Fres may overwrite it

    if (isF) {          // write F partial into Fres (aliases smF[0..4095])
#pragma unroll
        for (int m = 0; m < 4; m++) {
            *(float4*)&smF[(f_ty * 4 + m) * 64 + f_tx * 8] =
                make_float4(accT[m][0], accT[m][1], accT[m][2], accT[m][3]);
            *(float4*)&smF[(f_ty * 4 + m) * 64 + f_tx * 8 + 4] =
                make_float4(accT[m][4], accT[m][5], accT[m][6], accT[m][7]);
        }
    }
    __syncthreads();   // Fres visible to H warps

    if (!isF) {        // combine F + H, single write to g_Z
#pragma unroll
        for (int mi = 0; mi < 2; mi++) {
            const int r0 = wm * 32 + mi * 16 + g;
#pragma unroll
            for (int ni = 0; ni < 4; ni++) {
                const int col = wn2 * 32 + ni * 8 + 2 * l4;
                float2 fa = *(const float2*)&smF[r0 * 64 + col];
                float2 fb = *(const float2*)&smF[(r0 + 8) * 64 + col];
                float2 o0, o1;
                o0.x = __fadd_rn(accH[mi][ni][0], fa.x);
                o0.y = __fadd_rn(accH[mi][ni][1], fa.y);
                o1.x = __fadd_rn(accH[mi][ni][2], fb.x);
                o1.y = __fadd_rn(accH[mi][ni][3], fb.y);
                *(float2*)&g_Z[(size_t)(m0 + r0) * H_ + n0 + col]     = o0;
                *(float2*)&g_Z[(size_t)(m0 + r0 + 8) * H_ + n0 + col] = o1;
            }
        }
    }
}

// ---------------------------------------------------------------------------
// Pass 2: per-batch LIF scans (unchanged).
// ---------------------------------------------------------------------------
__global__ __launch_bounds__(128) void snn_scan_kernel(
    const float* __restrict__ b1, const float* __restrict__ W2,
    const float* __restrict__ b2, float* __restrict__ out)
{
    __shared__ unsigned s1w[T_ * 4];
    __shared__ float    W2s[H_ * C_];
    __shared__ float    dd[T_ * C_];

    const int b    = blockIdx.x;
    const int tid  = threadIdx.x;
    const int lane = tid & 31;
    const int warp = tid >> 5;

    for (int i = tid; i < H_ * C_; i += 128) W2s[i] = W2[i];

    const float b1h = b1[tid];
    const float* zp = g_Z + (size_t)b * T_ * H_ + tid;
    float v1 = 0.0f;

    float zbuf[20];
#pragma unroll
    for (int j = 0; j < 20; j++) zbuf[j] = zp[j * H_];

    for (int c = 0; c < 5; c++) {
        float znext[20];
        if (c < 4) {
#pragma unroll
            for (int j = 0; j < 20; j++)
                znext[j] = zp[(c * 20 + 20 + j) * H_];
        }
#pragma unroll
        for (int j = 0; j < 20; j++) {
            const int t = c * 20 + j;
            v1 = __fadd_rn(fmaf(v1, DECAY1, zbuf[j]), b1h);
            bool s = (v1 >= 1.0f);
            if (s) v1 = 0.0f;
            unsigned m = __ballot_sync(0xffffffffu, s);
            if (lane == 0) s1w[t * 4 + warp] = m;
        }
        if (c < 4) {
#pragma unroll
            for (int j = 0; j < 20; j++) zbuf[j] = znext[j];
        }
    }
    __syncthreads();

    for (int p = tid; p < T_ * C_; p += 128) {
        const int t = p / C_;
        const int c = p - t * C_;
        float sum = 0.0f;
#pragma unroll
        for (int w = 0; w < 4; w++) {
            const unsigned msk = s1w[t * 4 + w];
            const float* wp = &W2s[w * 32 * C_ + c];
#pragma unroll
            for (int bit = 0; bit < 32; bit++) {
                if (msk & (1u << bit)) sum = __fadd_rn(sum, wp[bit * C_]);
            }
        }
        dd[p] = sum;
    }
    __syncthreads();

    if (tid < C_) {
        const float b2c = b2[tid];
        float v2 = 0.0f, acc = 0.0f;
        for (int t = 0; t < T_; t++) {
            v2 = __fadd_rn(fmaf(v2, DECAY2, dd[t * C_ + tid]), b2c);
            if (v2 >= 1.0f) { acc += 1.0f; v2 = 0.0f; }
        }
        out[b * C_ + tid] = acc / (float)T_;
    }
}

// ---------------------------------------------------------------------------
// kernel_launch
// inputs: event_stream[256,100,1024] f32, W1[1024,128], b1[128], W2[128,5], b2[5]
// output: [256,5] f32
// ---------------------------------------------------------------------------
extern "C" void kernel_launch(void* const* d_in, const int* in_sizes, int n_in,
                              void* d_out, int out_size)
{
    const float* ev = (const float*)d_in[0];
    const float* W1 = (const float*)d_in[1];
    const float* b1 = (const float*)d_in[2];
    const float* W2 = (const float*)d_in[3];
    const float* b2 = (const float*)d_in[4];
    float* out = (float*)d_out;

    w1_convert<<<256, 256>>>(W1);
    snn_gemm_hybrid<<<800, 256>>>(ev, W1);
    snn_scan_kernel<<<B_, 128>>>(b1, W2, b2, out);
}